// round 4
// baseline (speedup 1.0000x reference)
#include <cuda_runtime.h>
#include <cuda_bf16.h>
#include <cstdint>
#include <cstddef>

typedef __nv_bfloat16 bf16;

#define BATCH 256
#define TT    128
#define DD    1024
#define HH    1024
#define GG    3072
#define BT    (BATCH*TT)   // 32768

// ---------------- device scratch (static; no runtime allocation) ----------------
__device__ float g_gi[(size_t)BT * GG];                 // 402 MB
__device__ bf16  g_xhi[(size_t)BT * DD];
__device__ bf16  g_xlo[(size_t)BT * DD];
__device__ bf16  g_wih_hi[(size_t)GG * DD];
__device__ bf16  g_wih_lo[(size_t)GG * DD];
__device__ bf16  g_whh_hi[(size_t)GG * HH];
__device__ bf16  g_whh_lo[(size_t)GG * HH];
__device__ float g_h[2][BATCH * HH];
__device__ bf16  g_hhi[2][BATCH * HH];
__device__ bf16  g_hlo[2][BATCH * HH];
__device__ float g_mask[BT];

// ---------------- helpers ----------------
__device__ __forceinline__ void cp16(uint32_t dst, const void* src) {
    asm volatile("cp.async.cg.shared.global [%0], [%1], 16;\n" :: "r"(dst), "l"(src));
}
__device__ __forceinline__ void cp_commit() { asm volatile("cp.async.commit_group;\n"); }
template<int N> __device__ __forceinline__ void cp_wait() {
    asm volatile("cp.async.wait_group %0;\n" :: "n"(N));
}
__device__ __forceinline__ void ldm4(uint32_t* r, uint32_t a) {
    asm volatile("ldmatrix.sync.aligned.m8n8.x4.shared.b16 {%0,%1,%2,%3},[%4];\n"
                 : "=r"(r[0]), "=r"(r[1]), "=r"(r[2]), "=r"(r[3]) : "r"(a));
}
__device__ __forceinline__ void ldm2(uint32_t* r, uint32_t a) {
    asm volatile("ldmatrix.sync.aligned.m8n8.x2.shared.b16 {%0,%1},[%2];\n"
                 : "=r"(r[0]), "=r"(r[1]) : "r"(a));
}
__device__ __forceinline__ void mma16816(float* c, const uint32_t* a, const uint32_t* b) {
    asm volatile("mma.sync.aligned.m16n8k16.row.col.f32.bf16.bf16.f32 "
                 "{%0,%1,%2,%3},{%4,%5,%6,%7},{%8,%9},{%0,%1,%2,%3};\n"
                 : "+f"(c[0]), "+f"(c[1]), "+f"(c[2]), "+f"(c[3])
                 : "r"(a[0]), "r"(a[1]), "r"(a[2]), "r"(a[3]), "r"(b[0]), "r"(b[1]));
}
// smem rows are 64B (32 halves); chunk = 16B unit; XOR swizzle on (row&3)
__device__ __forceinline__ uint32_t sw(uint32_t base, int r, int c) {
    return base + (r << 6) + ((c ^ (r & 3)) << 4);
}
__device__ __forceinline__ float sigmoidf_(float x) { return 1.f / (1.f + expf(-x)); }

// ---------------- prep kernels ----------------
__global__ void mask_kernel(const void* __restrict__ isin) {
    __shared__ int is32;
    if (threadIdx.x == 0) {
        const unsigned char* p = (const unsigned char*)isin;
        int ok = 1;
        for (int i = 0; i < 1024; i++) {
            if (p[4 * i + 1] | p[4 * i + 2] | p[4 * i + 3]) { ok = 0; break; }
        }
        is32 = ok;
    }
    __syncthreads();
    int start = blockIdx.x * blockDim.x + threadIdx.x;
    int stride = gridDim.x * blockDim.x;
    if (is32) {
        const int* q = (const int*)isin;
        for (int i = start; i < BT; i += stride) g_mask[i] = q[i] ? 0.f : 1.f;
    } else {
        const unsigned char* q = (const unsigned char*)isin;
        for (int i = start; i < BT; i += stride) g_mask[i] = q[i] ? 0.f : 1.f;
    }
}

__global__ void split_x_kernel(const float* __restrict__ x) {
    size_t n = (size_t)BT * DD;
    for (size_t i = blockIdx.x * (size_t)blockDim.x + threadIdx.x; i < n;
         i += (size_t)gridDim.x * blockDim.x) {
        float f = x[i];
        bf16 h = __float2bfloat16(f);
        g_xhi[i] = h;
        g_xlo[i] = __float2bfloat16(f - __bfloat162float(h));
    }
}
__global__ void split_wih_kernel(const float* __restrict__ w) {
    size_t n = (size_t)GG * DD;
    for (size_t i = blockIdx.x * (size_t)blockDim.x + threadIdx.x; i < n;
         i += (size_t)gridDim.x * blockDim.x) {
        float f = w[i];
        bf16 h = __float2bfloat16(f);
        g_wih_hi[i] = h;
        g_wih_lo[i] = __float2bfloat16(f - __bfloat162float(h));
    }
}
__global__ void split_whh_kernel(const float* __restrict__ w) {
    size_t n = (size_t)GG * HH;
    for (size_t i = blockIdx.x * (size_t)blockDim.x + threadIdx.x; i < n;
         i += (size_t)gridDim.x * blockDim.x) {
        float f = w[i];
        bf16 h = __float2bfloat16(f);
        g_whh_hi[i] = h;
        g_whh_lo[i] = __float2bfloat16(f - __bfloat162float(h));
    }
}
__global__ void init_h_kernel(const float* __restrict__ hx) {
    int n = BATCH * HH;
    for (int i = blockIdx.x * blockDim.x + threadIdx.x; i < n; i += gridDim.x * blockDim.x) {
        float f = hx[i];
        g_h[0][i] = f;
        bf16 h = __float2bfloat16(f);
        g_hhi[0][i] = h;
        g_hlo[0][i] = __float2bfloat16(f - __bfloat162float(h));
    }
}

// ---------------- gi = x @ W_ih^T + b_ih (split-bf16, 3-MMA) ----------------
// grid (GG/64, BT/128), block 256
__global__ __launch_bounds__(256) void gi_gemm(const float* __restrict__ b_ih) {
    __shared__ __align__(16) char smem[49152];
    uint32_t sb = (uint32_t)__cvta_generic_to_shared(smem);
    // per stage s: offset s*24576: Ahi 0 (128x64B), Alo 8192, Bhi 16384 (64x64B), Blo 20480
    int tid = threadIdx.x, lane = tid & 31, w = tid >> 5;
    int wm = w & 3, wn = w >> 2;
    int m0 = blockIdx.y * 128, n0 = blockIdx.x * 64;

    float acc[2][4][4];
#pragma unroll
    for (int i = 0; i < 2; i++)
#pragma unroll
        for (int j = 0; j < 4; j++)
#pragma unroll
            for (int e = 0; e < 4; e++) acc[i][j][e] = 0.f;

    auto load_stage = [&](int kt, int s) {
        uint32_t o = sb + s * 24576;
        int k0 = kt * 32;
#pragma unroll
        for (int v = tid; v < 512; v += 256) {
            int r = v >> 2, c = v & 3;
            const bf16* sh = g_xhi + (size_t)(m0 + r) * DD + k0 + c * 8;
            const bf16* sl = g_xlo + (size_t)(m0 + r) * DD + k0 + c * 8;
            cp16(sw(o, r, c), sh);
            cp16(sw(o + 8192, r, c), sl);
        }
        {
            int v = tid;
            int r = v >> 2, c = v & 3;
            cp16(sw(o + 16384, r, c), g_wih_hi + (size_t)(n0 + r) * DD + k0 + c * 8);
            cp16(sw(o + 20480, r, c), g_wih_lo + (size_t)(n0 + r) * DD + k0 + c * 8);
        }
        cp_commit();
    };

    load_stage(0, 0);
    const int KT = DD / 32;
    for (int kt = 0; kt < KT; kt++) {
        if (kt + 1 < KT) load_stage(kt + 1, (kt + 1) & 1);
        if (kt + 1 < KT) cp_wait<1>(); else cp_wait<0>();
        __syncthreads();
        uint32_t o = sb + (kt & 1) * 24576;
#pragma unroll
        for (int kk = 0; kk < 2; kk++) {
            uint32_t ah[2][4], al[2][4], bh[4][2], bl[4][2];
#pragma unroll
            for (int i = 0; i < 2; i++) {
                int r = wm * 32 + i * 16 + (lane & 15);
                int c = kk * 2 + (lane >> 4);
                ldm4(ah[i], sw(o, r, c));
                ldm4(al[i], sw(o + 8192, r, c));
            }
#pragma unroll
            for (int sg = 0; sg < 2; sg++) {
                int r = wn * 32 + sg * 16 + ((lane >> 4) & 1) * 8 + (lane & 7);
                int c = kk * 2 + ((lane >> 3) & 1);
                uint32_t t4[4];
                ldm4(t4, sw(o + 16384, r, c));
                bh[sg * 2][0] = t4[0]; bh[sg * 2][1] = t4[1];
                bh[sg * 2 + 1][0] = t4[2]; bh[sg * 2 + 1][1] = t4[3];
                ldm4(t4, sw(o + 20480, r, c));
                bl[sg * 2][0] = t4[0]; bl[sg * 2][1] = t4[1];
                bl[sg * 2 + 1][0] = t4[2]; bl[sg * 2 + 1][1] = t4[3];
            }
#pragma unroll
            for (int i = 0; i < 2; i++)
#pragma unroll
                for (int j = 0; j < 4; j++) {
                    mma16816(acc[i][j], ah[i], bh[j]);
                    mma16816(acc[i][j], ah[i], bl[j]);
                    mma16816(acc[i][j], al[i], bh[j]);
                }
        }
        __syncthreads();
    }

#pragma unroll
    for (int i = 0; i < 2; i++) {
        int row = m0 + wm * 32 + i * 16 + (lane >> 2);
#pragma unroll
        for (int j = 0; j < 4; j++) {
            int col = n0 + wn * 32 + j * 8 + (lane & 3) * 2;
            float b0 = b_ih[col], b1 = b_ih[col + 1];
            g_gi[(size_t)row * GG + col]           = acc[i][j][0] + b0;
            g_gi[(size_t)row * GG + col + 1]       = acc[i][j][1] + b1;
            g_gi[(size_t)(row + 8) * GG + col]     = acc[i][j][2] + b0;
            g_gi[(size_t)(row + 8) * GG + col + 1] = acc[i][j][3] + b1;
        }
    }
}

// ---------------- one GRU step: gh = h@W_hh^T (3 gates) + fused gate epilogue ----------------
// grid (HH/32, BATCH/64), block 256
__global__ __launch_bounds__(256) void gru_step(const float* __restrict__ b_hh,
                                                float* __restrict__ hseq_out, int t) {
    int cur = t & 1, nxt = cur ^ 1;
    __shared__ __align__(16) char smem[40960];
    uint32_t sb = (uint32_t)__cvta_generic_to_shared(smem);
    // per stage s: offset s*20480: Ahi 0 (64x64B), Alo 4096, Bhi 8192 (96x64B), Blo 14336
    int tid = threadIdx.x, lane = tid & 31, w = tid >> 5;
    int wm = w & 1, wn = w >> 1;
    int m0 = blockIdx.y * 64, n0 = blockIdx.x * 32;

    float acc[3][2][4];
#pragma unroll
    for (int g = 0; g < 3; g++)
#pragma unroll
        for (int i = 0; i < 2; i++)
#pragma unroll
            for (int e = 0; e < 4; e++) acc[g][i][e] = 0.f;

    auto load_stage = [&](int kt, int s) {
        uint32_t o = sb + s * 20480;
        int k0 = kt * 32;
        {
            int v = tid;  // 64 rows x 4 chunks = 256 exactly
            int r = v >> 2, c = v & 3;
            cp16(sw(o, r, c), g_hhi[cur] + (size_t)(m0 + r) * HH + k0 + c * 8);
            cp16(sw(o + 4096, r, c), g_hlo[cur] + (size_t)(m0 + r) * HH + k0 + c * 8);
        }
#pragma unroll
        for (int v = tid; v < 384; v += 256) {  // 96 rows x 4 chunks
            int r = v >> 2, c = v & 3;
            size_t grow = (size_t)((r >> 5) * HH + n0 + (r & 31));
            cp16(sw(o + 8192, r, c), g_whh_hi + grow * HH + k0 + c * 8);
            cp16(sw(o + 14336, r, c), g_whh_lo + grow * HH + k0 + c * 8);
        }
        cp_commit();
    };

    load_stage(0, 0);
    const int KT = HH / 32;
    for (int kt = 0; kt < KT; kt++) {
        if (kt + 1 < KT) load_stage(kt + 1, (kt + 1) & 1);
        if (kt + 1 < KT) cp_wait<1>(); else cp_wait<0>();
        __syncthreads();
        uint32_t o = sb + (kt & 1) * 20480;
#pragma unroll
        for (int kk = 0; kk < 2; kk++) {
            uint32_t ah[2][4], al[2][4], bh[3][2], bl[3][2];
#pragma unroll
            for (int i = 0; i < 2; i++) {
                int r = wm * 32 + i * 16 + (lane & 15);
                int c = kk * 2 + (lane >> 4);
                ldm4(ah[i], sw(o, r, c));
                ldm4(al[i], sw(o + 4096, r, c));
            }
#pragma unroll
            for (int g = 0; g < 3; g++) {
                int l = lane & 15;
                int r = g * 32 + wn * 8 + (l & 7);
                int c = kk * 2 + (l >> 3);
                ldm2(bh[g], sw(o + 8192, r, c));
                ldm2(bl[g], sw(o + 14336, r, c));
            }
#pragma unroll
            for (int g = 0; g < 3; g++)
#pragma unroll
                for (int i = 0; i < 2; i++) {
                    mma16816(acc[g][i], ah[i], bh[g]);
                    mma16816(acc[g][i], ah[i], bl[g]);
                    mma16816(acc[g][i], al[i], bh[g]);
                }
        }
        __syncthreads();
    }

    // fused gate epilogue
#pragma unroll
    for (int i = 0; i < 2; i++) {
        int rbase = m0 + wm * 32 + i * 16 + (lane >> 2);
        int cbase = n0 + wn * 8 + (lane & 3) * 2;
#pragma unroll
        for (int e = 0; e < 4; e++) {
            int bb = rbase + ((e >> 1) << 3);
            int hc = cbase + (e & 1);
            float m = g_mask[bb * TT + t];
            float ghr = acc[0][i][e] * m + b_hh[hc];
            float ghz = acc[1][i][e] * m + b_hh[1024 + hc];
            float ghn = acc[2][i][e] * m + b_hh[2048 + hc];
            const float* gi = g_gi + ((size_t)bb * TT + t) * GG + hc;
            float r = sigmoidf_(gi[0] + ghr);
            float z = sigmoidf_(gi[1024] + ghz);
            float n = tanhf(gi[2048] + r * ghn);
            float hp = g_h[cur][bb * HH + hc];
            float hn2 = (1.f - z) * n + z * (m * hp);
            int idx = bb * HH + hc;
            g_h[nxt][idx] = hn2;
            bf16 hhi = __float2bfloat16(hn2);
            g_hhi[nxt][idx] = hhi;
            g_hlo[nxt][idx] = __float2bfloat16(hn2 - __bfloat162float(hhi));
            hseq_out[((size_t)bb * TT + t) * HH + hc] = hn2;
        }
    }
}

// ---------------- LayerNorm + gated residual ----------------
__device__ __forceinline__ float block_sum(float v, float* red) {
#pragma unroll
    for (int o = 16; o; o >>= 1) v += __shfl_xor_sync(0xffffffffu, v, o);
    int w = threadIdx.x >> 5;
    if ((threadIdx.x & 31) == 0) red[w] = v;
    __syncthreads();
    if (threadIdx.x < 32) {
        float r = (threadIdx.x < 8) ? red[threadIdx.x] : 0.f;
#pragma unroll
        for (int o = 4; o; o >>= 1) r += __shfl_xor_sync(0xffffffffu, r, o);
        if (threadIdx.x == 0) red[0] = r;
    }
    __syncthreads();
    float out = red[0];
    __syncthreads();
    return out;
}

__global__ __launch_bounds__(256) void ln_kernel(const float* __restrict__ x,
                                                 const float* __restrict__ ln_g,
                                                 const float* __restrict__ ln_b,
                                                 const float* __restrict__ res_gate,
                                                 const float* __restrict__ hseq,
                                                 float* __restrict__ y) {
    __shared__ float red[8];
    int row = blockIdx.x;
    int tid = threadIdx.x;
    const float* hr = hseq + (size_t)row * HH;
    float v[4];
    float s = 0.f;
#pragma unroll
    for (int j = 0; j < 4; j++) { v[j] = hr[tid + j * 256]; s += v[j]; }
    float mu = block_sum(s, red) * (1.f / HH);
    float s2 = 0.f;
#pragma unroll
    for (int j = 0; j < 4; j++) { float d = v[j] - mu; s2 += d * d; }
    float var = block_sum(s2, red) * (1.f / HH);
    float rstd = rsqrtf(var + 1e-5f);
#pragma unroll
    for (int j = 0; j < 4; j++) {
        int hc = tid + j * 256;
        float gate = 1.f / (1.f + expf(-res_gate[hc]));
        y[(size_t)row * HH + hc] =
            (v[j] - mu) * rstd * ln_g[hc] + ln_b[hc] + x[(size_t)row * HH + hc] * gate;
    }
}

// ---------------- launch ----------------
extern "C" void kernel_launch(void* const* d_in, const int* in_sizes, int n_in,
                              void* d_out, int out_size) {
    const float* x        = (const float*)d_in[0];
    const float* hx       = (const float*)d_in[1];
    const void*  isin     = d_in[2];
    const float* W_ih     = (const float*)d_in[3];
    const float* W_hh     = (const float*)d_in[4];
    const float* b_ih     = (const float*)d_in[5];
    const float* b_hh     = (const float*)d_in[6];
    const float* ln_g     = (const float*)d_in[7];
    const float* ln_b     = (const float*)d_in[8];
    const float* res_gate = (const float*)d_in[9];
    float* out  = (float*)d_out;
    float* Y    = out;
    float* Hseq = out + (size_t)BT * HH;

    mask_kernel<<<32, 256>>>(isin);
    split_x_kernel<<<2048, 256>>>(x);
    split_wih_kernel<<<512, 256>>>(W_ih);
    split_whh_kernel<<<512, 256>>>(W_hh);
    init_h_kernel<<<256, 256>>>(hx);

    dim3 g1(GG / 64, BT / 128);
    gi_gemm<<<g1, 256>>>(b_ih);

    dim3 g2(HH / 32, BATCH / 64);
    for (int t = 0; t < TT; t++) gru_step<<<g2, 256>>>(b_hh, Hseq, t);

    ln_kernel<<<BT, 256>>>(x, ln_g, ln_b, res_gate, Hseq, Y);
}